// round 12
// baseline (speedup 1.0000x reference)
#include <cuda_runtime.h>
#include <cuda_fp16.h>
#include <cstdint>

#define BATCH 2048
#define NTOK 64
#define DIM 512
#define HEADS 16
#define QKV 1536
#define MTOT (BATCH * NTOK)      // 131072 rows

// ---------------------------------------------------------------------------
// Scratch (static __device__ globals; no allocations allowed)
// ---------------------------------------------------------------------------
__device__ __half g_xh[(size_t)MTOT * DIM];      // 134 MB: x in fp16
__device__ __half g_attnh[(size_t)MTOT * DIM];   // 134 MB: attention out (fp16)
__device__ __half g_wqkvth[QKV * DIM];           // w_qkv^T  [1536][512] fp16
__device__ __half g_wprojth[DIM * DIM];          // w_proj^T [512][512] fp16
__device__ float g_Kss[NTOK * NTOK];             // gaussian * softmax scale

// ---------------------------------------------------------------------------
// PTX helpers
// ---------------------------------------------------------------------------
__device__ __forceinline__ uint32_t smem_u32(const void* p) {
    uint32_t a;
    asm("{ .reg .u64 t; cvta.to.shared.u64 t, %1; cvt.u32.u64 %0, t; }"
        : "=r"(a) : "l"(p));
    return a;
}

__device__ __forceinline__ void cp16(uint32_t dst, const void* src) {
    asm volatile("cp.async.cg.shared.global [%0], [%1], 16;"
                 :: "r"(dst), "l"(src));
}
#define CP_COMMIT() asm volatile("cp.async.commit_group;")
#define CP_WAIT(N) asm volatile("cp.async.wait_group %0;" :: "n"(N))

#define LDSM_X4(R0, R1, R2, R3, ADDR) \
    asm volatile("ldmatrix.sync.aligned.m8n8.x4.shared.b16 {%0,%1,%2,%3}, [%4];" \
                 : "=r"(R0), "=r"(R1), "=r"(R2), "=r"(R3) : "r"(ADDR))
#define LDSM_X4_T(R0, R1, R2, R3, ADDR) \
    asm volatile("ldmatrix.sync.aligned.m8n8.x4.trans.shared.b16 {%0,%1,%2,%3}, [%4];" \
                 : "=r"(R0), "=r"(R1), "=r"(R2), "=r"(R3) : "r"(ADDR))

__device__ __forceinline__ void mma16816(float c[4], const uint32_t a[4],
                                         uint32_t b0, uint32_t b1) {
    asm volatile(
        "mma.sync.aligned.m16n8k16.row.col.f32.f16.f16.f32 "
        "{%0,%1,%2,%3}, {%4,%5,%6,%7}, {%8,%9}, {%0,%1,%2,%3};"
        : "+f"(c[0]), "+f"(c[1]), "+f"(c[2]), "+f"(c[3])
        : "r"(a[0]), "r"(a[1]), "r"(a[2]), "r"(a[3]), "r"(b0), "r"(b1));
}

__device__ __forceinline__ uint32_t pack_h2(float x, float y) {
    half2 h = __floats2half2_rn(x, y);
    return *(uint32_t*)&h;
}

// ---------------------------------------------------------------------------
// x fp32 -> fp16, with Kss precompute folded into block 0
// ---------------------------------------------------------------------------
__global__ void cvt_x_kss_kernel(const float* __restrict__ x) {
    if (blockIdx.x == 0 && threadIdx.x < 64) {
        const int i = threadIdx.x;
        const float yi = (float)(i >> 3), xi = (float)(i & 7);
        const float inv2s2 = 1.0f / (2.0f * 0.39f * 0.39f);
        float row[64];
        float s = 0.f;
#pragma unroll
        for (int j = 0; j < 64; ++j) {
            float dy = yi - (float)(j >> 3);
            float dx = xi - (float)(j & 7);
            float e = __expf(-(dy * dy + dx * dx) * inv2s2);
            row[j] = e;
            s += e;
        }
        const float inv = 0.17677669529663688f / s;  // scale / rowsum
#pragma unroll
        for (int j = 0; j < 64; ++j) g_Kss[i * 64 + j] = row[j] * inv;
    }
    const size_t i = ((size_t)blockIdx.x * 256 + threadIdx.x) * 8;
    float4 a = *(const float4*)(x + i);
    float4 b = *(const float4*)(x + i + 4);
    __half h[8];
    h[0] = __float2half_rn(a.x); h[1] = __float2half_rn(a.y);
    h[2] = __float2half_rn(a.z); h[3] = __float2half_rn(a.w);
    h[4] = __float2half_rn(b.x); h[5] = __float2half_rn(b.y);
    h[6] = __float2half_rn(b.z); h[7] = __float2half_rn(b.w);
    *(uint4*)(&g_xh[i]) = *(uint4*)h;
}

// ---------------------------------------------------------------------------
// Both weight transposes in one kernel: dst[n][k] = h(src[k][n]); K = 512
// grid (48, 32): by<16 -> wqkv (bx<48), by>=16 -> wproj (bx<16)
// ---------------------------------------------------------------------------
__global__ void transpose_cvt_both_kernel(const float* __restrict__ wqkv,
                                          const float* __restrict__ wproj) {
    __shared__ float t[32][33];
    int byi = blockIdx.y;
    const float* src;
    __half* dst;
    int N;
    if (byi < 16) {
        src = wqkv; dst = (__half*)g_wqkvth; N = QKV;
    } else {
        if (blockIdx.x >= 16) return;
        byi -= 16;
        src = wproj; dst = (__half*)g_wprojth; N = DIM;
    }
    const int bx = blockIdx.x * 32;  // n
    const int by = byi * 32;         // k
    const int x = threadIdx.x, y = threadIdx.y;  // 32 x 8
#pragma unroll
    for (int i = 0; i < 32; i += 8)
        t[y + i][x] = src[(size_t)(by + y + i) * N + bx + x];
    __syncthreads();
#pragma unroll
    for (int i = 0; i < 32; i += 8)
        dst[(size_t)(bx + y + i) * 512 + by + x] = __float2half_rn(t[x][y + i]);
}

// ===========================================================================
// FUSED QKV-GEMM + ATTENTION, QK-interleaved over shared A tile.
// Grid: 1024 CTAs (one per 2 batches = 128 rows), 256 thr = 8 warps.
// Per chunk c (4 heads): pass QK (8 k-tiles, A + B_Q + B_K per tile, 32
// indep MMAs per kk), then pass V (8 k-tiles, A + B_V). 64 global tiles,
// 2-stage pipeline, continuous load stream across passes/chunks so the
// attention phase overlaps the next chunk's loads.
// smem: 2 stages x (A 18432 | B0 18432 | B1 18432) = 110592 |
//       Q@110592 K@145408 V@180224 (stride 272B) -> total 215040
// ===========================================================================
#define STAGE_SZ 55296
#define FOFF_Q  110592
#define FOFF_K  145408
#define FOFF_V  180224
#define FSM_TOTAL 215040
#define STG_STRIDE 272   // bytes per 128-col fp16 staging row (256 + 16 pad)

__global__ void __launch_bounds__(256, 1) fused_qkv_attn_kernel(
    const float* __restrict__ b_qkv) {
    extern __shared__ char sm[];
    const uint32_t sb = smem_u32(sm);
    const int tid = threadIdx.x;
    const int lane = tid & 31;
    const int wid = tid >> 5;
    const int wm = wid >> 1;  // 0..3 -> GEMM m offset wm*32
    const int wn = wid & 1;   // 0..1 -> GEMM n offset wn*64
    const int bp = blockIdx.x;        // batch pair
    const size_t rowbase = (size_t)bp * 128;

    // loader mapping: 8 lanes per 128B k-slice row
    const int lr = tid >> 3;       // 0..31
    const int lc = tid & 7;        // 16B chunk
    const char* Abase = (const char*)(g_xh + (rowbase + lr) * 512) + lc * 16;
    const uint32_t dstoff = (uint32_t)(lr * 144 + lc * 16);

    const int g4 = lane >> 2, t4 = lane & 3;
    const int iw = wid >> 2;   // attention: batch half 0..1
    const int hl = wid & 3;    // attention: local head 0..3

    // tile g (0..63): c=g>>4, i=g&15. i<8: QK pass (kt=i); else V pass (kt=i-8)
#define ISSUE_LOAD(G) do { \
    const int _g = (G); \
    const int _c = _g >> 4; \
    const int _i = _g & 15; \
    const uint32_t _buf = sb + (uint32_t)(_g & 1) * STAGE_SZ; \
    if (_i < 8) { \
        const int _kt = _i; \
        const char* _Bq = (const char*)(g_wqkvth + (size_t)(_c * 128 + lr) * 512) + \
                          lc * 16 + _kt * 128; \
        const char* _Bk = _Bq + (size_t)512 * 1024; \
        _Pragma("unroll") \
        for (int it = 0; it < 4; ++it) \
            cp16(_buf + dstoff + it * 32 * 144, \
                 Abase + (size_t)it * 32 * 1024 + _kt * 128); \
        _Pragma("unroll") \
        for (int it = 0; it < 4; ++it) \
            cp16(_buf + 18432 + dstoff + it * 32 * 144, _Bq + (size_t)it * 32 * 1024); \
        _Pragma("unroll") \
        for (int it = 0; it < 4; ++it) \
            cp16(_buf + 36864 + dstoff + it * 32 * 144, _Bk + (size_t)it * 32 * 1024); \
    } else { \
        const int _kt = _i - 8; \
        const char* _Bv = (const char*)(g_wqkvth + \
                          (size_t)(1024 + _c * 128 + lr) * 512) + lc * 16 + _kt * 128; \
        _Pragma("unroll") \
        for (int it = 0; it < 4; ++it) \
            cp16(_buf + dstoff + it * 32 * 144, \
                 Abase + (size_t)it * 32 * 1024 + _kt * 128); \
        _Pragma("unroll") \
        for (int it = 0; it < 4; ++it) \
            cp16(_buf + 18432 + dstoff + it * 32 * 144, _Bv + (size_t)it * 32 * 1024); \
    } \
    CP_COMMIT(); \
} while (0)

    ISSUE_LOAD(0);
    ISSUE_LOAD(1);

    float accQ[2][8][4];   // QK pass: Q accum; V pass: V accum
    float accK[2][8][4];
#pragma unroll
    for (int mt = 0; mt < 2; ++mt)
#pragma unroll
        for (int nt = 0; nt < 8; ++nt)
#pragma unroll
            for (int e = 0; e < 4; ++e) { accQ[mt][nt][e] = 0.f; accK[mt][nt][e] = 0.f; }

    int g = 0;
#pragma unroll 1
    for (int c = 0; c < 4; ++c) {
        // ---------------- QK pass: 8 tiles ----------------
#pragma unroll 1
        for (int i = 0; i < 8; ++i, ++g) {
            CP_WAIT(1);
            __syncthreads();
            const uint32_t bufA = sb + (uint32_t)(g & 1) * STAGE_SZ;
#pragma unroll
            for (int kk = 0; kk < 4; ++kk) {
                uint32_t a[2][4], bq[4][4], bk[4][4];
#pragma unroll
                for (int mt = 0; mt < 2; ++mt) {
                    const uint32_t addr = bufA +
                        (wm * 32 + mt * 16 + (lane & 15)) * 144 +
                        kk * 32 + (lane >> 4) * 16;
                    LDSM_X4(a[mt][0], a[mt][1], a[mt][2], a[mt][3], addr);
                }
#pragma unroll
                for (int nb = 0; nb < 4; ++nb) {
                    const uint32_t nrow = (wn * 64 + nb * 16 + (lane & 15)) * 144 +
                                          kk * 32 + (lane >> 4) * 16;
                    LDSM_X4(bq[nb][0], bq[nb][1], bq[nb][2], bq[nb][3],
                            bufA + 18432 + nrow);
                    LDSM_X4(bk[nb][0], bk[nb][1], bk[nb][2], bk[nb][3],
                            bufA + 36864 + nrow);
                }
#pragma unroll
                for (int mt = 0; mt < 2; ++mt)
#pragma unroll
                    for (int nt = 0; nt < 8; ++nt) {
                        mma16816(accQ[mt][nt], a[mt], bq[nt >> 1][nt & 1],
                                 bq[nt >> 1][2 + (nt & 1)]);
                        mma16816(accK[mt][nt], a[mt], bk[nt >> 1][nt & 1],
                                 bk[nt >> 1][2 + (nt & 1)]);
                    }
            }
            // pass end: epilogue Q and K into staging
            if (i == 7) {
#pragma unroll
                for (int mt = 0; mt < 2; ++mt) {
                    const int r0 = wm * 32 + mt * 16 + g4;
#pragma unroll
                    for (int nt = 0; nt < 8; ++nt) {
                        const int c0 = wn * 64 + nt * 8 + 2 * t4;
                        const float2 bvq = *(const float2*)(b_qkv + c * 128 + c0);
                        const float2 bvk = *(const float2*)(b_qkv + 512 + c * 128 + c0);
                        *(half2*)(sm + FOFF_Q + r0 * STG_STRIDE + c0 * 2) =
                            __floats2half2_rn(accQ[mt][nt][0] + bvq.x,
                                              accQ[mt][nt][1] + bvq.y);
                        *(half2*)(sm + FOFF_Q + (r0 + 8) * STG_STRIDE + c0 * 2) =
                            __floats2half2_rn(accQ[mt][nt][2] + bvq.x,
                                              accQ[mt][nt][3] + bvq.y);
                        *(half2*)(sm + FOFF_K + r0 * STG_STRIDE + c0 * 2) =
                            __floats2half2_rn(accK[mt][nt][0] + bvk.x,
                                              accK[mt][nt][1] + bvk.y);
                        *(half2*)(sm + FOFF_K + (r0 + 8) * STG_STRIDE + c0 * 2) =
                            __floats2half2_rn(accK[mt][nt][2] + bvk.x,
                                              accK[mt][nt][3] + bvk.y);
#pragma unroll
                        for (int e = 0; e < 4; ++e) {
                            accQ[mt][nt][e] = 0.f;
                            accK[mt][nt][e] = 0.f;
                        }
                    }
                }
            }
            __syncthreads();
            if (g + 2 < 64) ISSUE_LOAD(g + 2);
        }
        // ---------------- V pass: 8 tiles (acc in accQ) ----------------
#pragma unroll 1
        for (int i = 0; i < 8; ++i, ++g) {
            CP_WAIT(1);
            __syncthreads();
            const uint32_t bufA = sb + (uint32_t)(g & 1) * STAGE_SZ;
#pragma unroll
            for (int kk = 0; kk < 4; ++kk) {
                uint32_t a[2][4], bv[4][4];
#pragma unroll
                for (int mt = 0; mt < 2; ++mt) {
                    const uint32_t addr = bufA +
                        (wm * 32 + mt * 16 + (lane & 15)) * 144 +
                        kk * 32 + (lane >> 4) * 16;
                    LDSM_X4(a[mt][0], a[mt][1], a[mt][2], a[mt][3], addr);
                }
#pragma unroll
                for (int nb = 0; nb < 4; ++nb) {
                    const uint32_t addr = bufA + 18432 +
                        (wn * 64 + nb * 16 + (lane & 15)) * 144 +
                        kk * 32 + (lane >> 4) * 16;
                    LDSM_X4(bv[nb][0], bv[nb][1], bv[nb][2], bv[nb][3], addr);
                }
#pragma unroll
                for (int mt = 0; mt < 2; ++mt)
#pragma unroll
                    for (int nt = 0; nt < 8; ++nt)
                        mma16816(accQ[mt][nt], a[mt], bv[nt >> 1][nt & 1],
                                 bv[nt >> 1][2 + (nt & 1)]);
            }
            if (i == 7) {
#pragma unroll
                for (int mt = 0; mt < 2; ++mt) {
                    const int r0 = wm * 32 + mt * 16 + g4;
#pragma unroll
                    for (int nt = 0; nt < 8; ++nt) {
                        const int c0 = wn * 64 + nt * 8 + 2 * t4;
                        const float2 bv2 = *(const float2*)(b_qkv + 1024 + c * 128 + c0);
                        *(half2*)(sm + FOFF_V + r0 * STG_STRIDE + c0 * 2) =
                            __floats2half2_rn(accQ[mt][nt][0] + bv2.x,
                                              accQ[mt][nt][1] + bv2.y);
                        *(half2*)(sm + FOFF_V + (r0 + 8) * STG_STRIDE + c0 * 2) =
                            __floats2half2_rn(accQ[mt][nt][2] + bv2.x,
                                              accQ[mt][nt][3] + bv2.y);
#pragma unroll
                        for (int e = 0; e < 4; ++e) accQ[mt][nt][e] = 0.f;
                    }
                }
            }
            __syncthreads();
            if (g + 2 < 64) ISSUE_LOAD(g + 2);
        }

        // ================= attention: one (iw, hl) block per warp =========
        {
            const uint32_t qst = sb + FOFF_Q;
            const uint32_t kst = sb + FOFF_K;
            const uint32_t vst = sb + FOFF_V;
            const uint32_t colb = (uint32_t)(hl * 64);  // byte offset of head cols

            // ---- S = Q K^T : 64 x 64, K=32 ----
            float s[4][8][4];
#pragma unroll
            for (int mt = 0; mt < 4; ++mt)
#pragma unroll
                for (int nt = 0; nt < 8; ++nt)
#pragma unroll
                    for (int e = 0; e < 4; ++e) s[mt][nt][e] = 0.f;

#pragma unroll
            for (int kk = 0; kk < 2; ++kk) {
                uint32_t aq[4][4];
#pragma unroll
                for (int mt = 0; mt < 4; ++mt)
                    LDSM_X4(aq[mt][0], aq[mt][1], aq[mt][2], aq[mt][3],
                            qst + (iw * 64 + mt * 16 + (lane & 15)) * STG_STRIDE +
                            colb + kk * 32 + (lane >> 4) * 16);
#pragma unroll
                for (int nb = 0; nb < 4; ++nb) {
                    uint32_t bk[4];
                    LDSM_X4(bk[0], bk[1], bk[2], bk[3],
                            kst + (iw * 64 + nb * 16 + (lane & 15)) * STG_STRIDE +
                            colb + kk * 32 + (lane >> 4) * 16);
#pragma unroll
                    for (int mt = 0; mt < 4; ++mt) {
                        mma16816(s[mt][nb * 2], aq[mt], bk[0], bk[2]);
                        mma16816(s[mt][nb * 2 + 1], aq[mt], bk[1], bk[3]);
                    }
                }
            }

            // ---- gaussian mask + softmax (per 16-row m-tile) ----
            float rA[4], rB[4];
#pragma unroll
            for (int mt = 0; mt < 4; ++mt) {
                const int iA = mt * 16 + g4;      // local token row
                const int iB = iA + 8;
                float mA = -1e30f, mB = -1e30f;
#pragma unroll
                for (int nt = 0; nt < 8; ++nt) {
                    const int j0 = nt * 8 + 2 * t4;
                    const float2 kA = *(const float2*)&g_Kss[iA * 64 + j0];
                    const float2 kB = *(const float2*)&g_Kss[iB * 64 + j0];
                    s[mt][nt][0] *= kA.x;
                    s[mt][nt][1] *= kA.y;
                    s[mt][nt][2] *= kB.x;
                    s[mt][nt][3] *= kB.y;
                    mA = fmaxf(mA, fmaxf(s[mt][nt][0], s[mt][nt][1]));
                    mB = fmaxf(mB, fmaxf(s[mt][nt][2], s[mt][nt][3]));
                }
                mA = fmaxf(mA, __shfl_xor_sync(0xffffffffu, mA, 1));
                mA = fmaxf(mA, __shfl_xor_sync(0xffffffffu, mA, 2));
                mB = fmaxf(mB, __shfl_xor_sync(0xffffffffu, mB, 1));
                mB = fmaxf(mB, __shfl_xor_sync(0xffffffffu, mB, 2));
                float sA_ = 0.f, sB_ = 0.f;
#pragma unroll
                for (int nt = 0; nt < 8; ++nt) {
                    s[mt][nt][0] = __expf(s[mt][nt][0] - mA);
                    s[mt][nt][1] = __expf(s[mt][nt][1] - mA);
                    s[mt][nt][2] = __expf(s[mt][nt][2] - mB);
                    s[mt][nt][3] = __expf(s[mt][nt][3] - mB);
                    sA_ += s[mt][nt][0] + s[mt][nt][1];
                    sB_ += s[mt][nt][2] + s[mt][nt][3];
                }
                sA_ += __shfl_xor_sync(0xffffffffu, sA_, 1);
                sA_ += __shfl_xor_sync(0xffffffffu, sA_, 2);
                sB_ += __shfl_xor_sync(0xffffffffu, sB_, 1);
                sB_ += __shfl_xor_sync(0xffffffffu, sB_, 2);
                rA[mt] = 1.0f / sA_;
                rB[mt] = 1.0f / sB_;
            }

            // ---- O = P V : 64 x 32, K=64 (P from registers) ----
            float o[4][4][4];
#pragma unroll
            for (int mt = 0; mt < 4; ++mt)
#pragma unroll
                for (int nt = 0; nt < 4; ++nt)
#pragma unroll
                    for (int e = 0; e < 4; ++e) o[mt][nt][e] = 0.f;

#pragma unroll
            for (int kk = 0; kk < 4; ++kk) {
                uint32_t vb0[4], vb1[4];
                LDSM_X4_T(vb0[0], vb0[1], vb0[2], vb0[3],
                          vst + (iw * 64 + kk * 16 + (lane & 15)) * STG_STRIDE +
                          colb + (lane >> 4) * 16);
                LDSM_X4_T(vb1[0], vb1[1], vb1[2], vb1[3],
                          vst + (iw * 64 + kk * 16 + (lane & 15)) * STG_STRIDE +
                          colb + 32 + (lane >> 4) * 16);
#pragma unroll
                for (int mt = 0; mt < 4; ++mt) {
                    uint32_t a[4];
                    a[0] = pack_h2(s[mt][2 * kk][0] * rA[mt], s[mt][2 * kk][1] * rA[mt]);
                    a[1] = pack_h2(s[mt][2 * kk][2] * rB[mt], s[mt][2 * kk][3] * rB[mt]);
                    a[2] = pack_h2(s[mt][2 * kk + 1][0] * rA[mt],
                                   s[mt][2 * kk + 1][1] * rA[mt]);
                    a[3] = pack_h2(s[mt][2 * kk + 1][2] * rB[mt],
                                   s[mt][2 * kk + 1][3] * rB[mt]);
                    mma16816(o[mt][0], a, vb0[0], vb0[1]);
                    mma16816(o[mt][1], a, vb0[2], vb0[3]);
                    mma16816(o[mt][2], a, vb1[0], vb1[1]);
                    mma16816(o[mt][3], a, vb1[2], vb1[3]);
                }
            }

            // ---- store O to g_attnh ----
            const int gcol0 = (c * 4 + hl) * 32;
#pragma unroll
            for (int mt = 0; mt < 4; ++mt) {
                const size_t grow = rowbase + iw * 64 + mt * 16 + g4;
#pragma unroll
                for (int nt = 0; nt < 4; ++nt) {
                    const int cc = gcol0 + nt * 8 + 2 * t4;
                    *(half2*)(g_attnh + grow * 512 + cc) =
                        __floats2half2_rn(o[mt][nt][0], o[mt][nt][1]);
                    *(half2*)(g_attnh + (grow + 8) * 512 + cc) =
                        __floats2half2_rn(o[mt][nt][2], o[mt][nt][3]);
                }
            }
        }
        // next chunk's first __syncthreads gates staging reuse
    }
#undef ISSUE_LOAD
}

// ---------------------------------------------------------------------------
// Proj GEMM (proven config): out[M,512] = attnh @ wprojT + bias
// CTA 128x128, 256 thr (8 warps 4m x 2n, warp 32x64), occ 2.
// ---------------------------------------------------------------------------
#define GSM_TOTAL 73728

__global__ void __launch_bounds__(256, 2) proj_gemm_kernel(
    const float* __restrict__ bias, float* __restrict__ CoutF) {
    const __half* __restrict__ A = (const __half*)g_attnh;
    const __half* __restrict__ Bt = (const __half*)g_wprojth;

    extern __shared__ char sm[];
    const uint32_t sb = smem_u32(sm);
    const int tid = threadIdx.x;
    const int lane = tid & 31;
    const int wid = tid >> 5;
    const int wm = wid >> 1;  // 0..3
    const int wn = wid & 1;   // 0..1

    const int brow = blockIdx.y * 128;
    const int bcol = blockIdx.x * 128;

    const int lr = tid >> 3;
    const int lc = tid & 7;
    const char* Abase = (const char*)(A + (size_t)(brow + lr) * 512) + lc * 16;
    const char* Bbase = (const char*)(Bt + (size_t)(bcol + lr) * 512) + lc * 16;
    const uint32_t sA[2] = {sb + 0, sb + 36864};
    const uint32_t sB[2] = {sb + 18432, sb + 55296};
    const uint32_t dstoff = (uint32_t)(lr * 144 + lc * 16);

    float c[2][8][4];
#pragma unroll
    for (int mt = 0; mt < 2; ++mt)
#pragma unroll
        for (int nt = 0; nt < 8; ++nt)
#pragma unroll
            for (int e = 0; e < 4; ++e) c[mt][nt][e] = 0.f;

#define PLOAD(KT, BUF) do { \
    _Pragma("unroll") \
    for (int it = 0; it < 4; ++it) \
        cp16(sA[BUF] + dstoff + it * 32 * 144, Abase + (size_t)it * 32 * 1024 + (KT) * 128); \
    _Pragma("unroll") \
    for (int it = 0; it < 4; ++it) \
        cp16(sB[BUF] + dstoff + it * 32 * 144, Bbase + (size_t)it * 32 * 1024 + (KT) * 128); \
    CP_COMMIT(); \
} while (0)

    PLOAD(0, 0);
    PLOAD(1, 1);

#pragma unroll 1
    for (int kt = 0; kt < 8; ++kt) {
        const int buf = kt & 1;
        if (kt < 7) { CP_WAIT(1); } else { CP_WAIT(0); }
        __syncthreads();
#pragma unroll
        for (int kk = 0; kk < 4; ++kk) {
            uint32_t a[2][4], b[4][4];
#pragma unroll
            for (int mt = 0; mt < 2; ++mt) {
                const uint32_t addr = sA[buf] + (wm * 32 + mt * 16 + (lane & 15)) * 144 +
                                      kk * 32 + (lane >> 4) * 16;
                LDSM_X4(a[mt][0], a[mt][1], a[mt][2], a[mt][3], addr);
            }
#pragma unroll
            for (int nb = 0; nb < 4; ++nb) {
                const uint32_t addr = sB[buf] + (wn * 64 + nb * 16 + (lane & 15)) * 144 +
                                      kk * 32 + (lane >> 4) * 16;
                LDSM_X4(b[nb][0], b[nb][1], b[nb][2], b[nb][3], addr);
            }
#pragma unroll
            for (int mt = 0; mt < 2; ++mt)
#pragma unroll
                for (int nt = 0; nt < 8; ++nt)
                    mma16816(c[mt][nt], a[mt], b[nt >> 1][nt & 1],
                             b[nt >> 1][2 + (nt & 1)]);
        }
        __syncthreads();
        if (kt + 2 < 8) PLOAD(kt + 2, buf);
    }
#undef PLOAD

    // epilogue: stage fp32 in smem, coalesced fp32 store
    float* es = (float*)sm;  // 128 x 132
    const int g = lane >> 2, t4 = lane & 3;
#pragma unroll
    for (int mt = 0; mt < 2; ++mt) {
        const int r0 = wm * 32 + mt * 16 + g;
#pragma unroll
        for (int nt = 0; nt < 8; ++nt) {
            const int c0 = wn * 64 + nt * 8 + 2 * t4;
            *(float2*)&es[r0 * 132 + c0] = make_float2(c[mt][nt][0], c[mt][nt][1]);
            *(float2*)&es[(r0 + 8) * 132 + c0] = make_float2(c[mt][nt][2], c[mt][nt][3]);
        }
    }
    __syncthreads();

    const int cb = (tid & 31) * 4;
    const float4 bv = *(const float4*)(bias + bcol + cb);
#pragma unroll
    for (int it = 0; it < 16; ++it) {
        const int row = (tid >> 5) + it * 8;
        float4 o;
        o.x = es[row * 132 + cb + 0] + bv.x;
        o.y = es[row * 132 + cb + 1] + bv.y;
        o.z = es[row * 132 + cb + 2] + bv.z;
        o.w = es[row * 132 + cb + 3] + bv.w;
        *(float4*)(CoutF + (size_t)(brow + row) * DIM + bcol + cb) = o;
    }
}

// ---------------------------------------------------------------------------
// Launch
// ---------------------------------------------------------------------------
extern "C" void kernel_launch(void* const* d_in, const int* in_sizes, int n_in,
                              void* d_out, int out_size) {
    (void)in_sizes;
    (void)n_in;
    (void)out_size;
    const float* x = (const float*)d_in[0];
    const float* w_qkv = (const float*)d_in[1];
    const float* b_qkv = (const float*)d_in[2];
    const float* w_proj = (const float*)d_in[3];
    const float* b_proj = (const float*)d_in[4];
    float* out = (float*)d_out;

    cudaFuncSetAttribute(fused_qkv_attn_kernel,
                         cudaFuncAttributeMaxDynamicSharedMemorySize, FSM_TOTAL);
    cudaFuncSetAttribute(proj_gemm_kernel,
                         cudaFuncAttributeMaxDynamicSharedMemorySize, GSM_TOTAL);

    cvt_x_kss_kernel<<<MTOT * DIM / 8 / 256, 256>>>(x);
    transpose_cvt_both_kernel<<<dim3(48, 32), dim3(32, 8)>>>(w_qkv, w_proj);
    fused_qkv_attn_kernel<<<BATCH / 2, 256, FSM_TOTAL>>>(b_qkv);
    proj_gemm_kernel<<<dim3(DIM / 128, MTOT / 128), 256, GSM_TOTAL>>>(b_proj, out);
}